// round 1
// baseline (speedup 1.0000x reference)
#include <cuda_runtime.h>
#include <math.h>

#define NX 64
#define NU 64
#define NUN 256
#define NY 32
#define NZ 384        // 2*NX + NUN
#define BATCH 32768
#define NSTATE 384    // 128 (z = x||u) + 256 (w)
#define TB 64         // batch elements (threads) per block

// ---------------- device scratch (no cudaMalloc allowed) ----------------
__device__ float g_lT1[NZ * 64];
__device__ float g_lT2[NZ * 32];
__device__ float g_M1[NZ * 64];
__device__ float g_M2[NZ * 32];
__device__ float g_H[256 * 320];     // H[64+r][c], r in [0,256), c in [0,320)
__device__ float g_invlam[256];
__device__ float g_MT[256 * NSTATE]; // row i: [C1[i,:]*il, D12[i,:]*il, A[i,:]*il]
__device__ float g_bias[256];        // b_w[i] / lam[i]
__device__ float g_D21T[256 * 32];   // [unit][y]
__device__ float g_by[32];

// ---------------- setup kernels (batch-independent weights) --------------

// lT1 (384x64), lT2 (384x32)
__global__ void k_build_lT(const float* __restrict__ B2, const float* __restrict__ C2,
                           const float* __restrict__ D12, const float* __restrict__ D21,
                           const float* __restrict__ St) {
    int r = blockIdx.x;      // 0..383
    int k = threadIdx.x;     // 0..63
    float v1;
    if (r < 64) {
        // (S_t @ C_2).T  -> lT1[r][k] = sum_m St[k][m] * C2[m][r]
        float s = 0.f;
        for (int m = 0; m < 32; m++) s += St[k * 32 + m] * C2[m * 64 + r];
        v1 = s;
    } else if (r < 320) {
        int rr = r - 64;
        float s = 0.f;
        for (int m = 0; m < 32; m++) s += St[k * 32 + m] * D21[m * 256 + rr];
        v1 = s - D12[rr * 64 + k]; // (S_t@D_21 - D_12.T).T
    } else {
        v1 = B2[(r - 320) * 64 + k];
    }
    g_lT1[r * 64 + k] = v1;
    if (k < 32) {
        float v2;
        if (r < 64)        v2 = C2[k * 64 + r];
        else if (r < 320)  v2 = D21[k * 256 + (r - 64)];
        else               v2 = 0.f;
        g_lT2[r * 32 + k] = v2;
    }
}

// M1 = lT1 @ Rinv, M2 = lT2 @ Q
__global__ void k_build_M(const float* __restrict__ Rinv, const float* __restrict__ Q) {
    int r = blockIdx.x, k = threadIdx.x;
    float s = 0.f;
    for (int t = 0; t < 64; t++) s += g_lT1[r * 64 + t] * Rinv[t * 64 + k];
    g_M1[r * 64 + k] = s;
    if (k < 32) {
        float s2 = 0.f;
        for (int t = 0; t < 32; t++) s2 += g_lT2[r * 32 + t] * Q[t * 32 + k];
        g_M2[r * 32 + k] = s2;
    }
}

// H[64+r][c] for r in [0,256), c in [0,320)
__global__ void k_build_H(const float* __restrict__ X) {
    int idx = blockIdx.x * blockDim.x + threadIdx.x;
    if (idx >= 256 * 320) return;
    int r = idx / 320, c = idx % 320;
    int a = 64 + r;
    float h = 0.f;
    for (int t = 0; t < NZ; t++) h += X[t * NZ + a] * X[t * NZ + c];
    if (c == a) h += 0.001f;
    float h1 = 0.f;
    for (int k = 0; k < 64; k++) h1 += g_M1[a * 64 + k] * g_lT1[c * 64 + k];
    float h2 = 0.f;
    for (int k = 0; k < 32; k++) h2 += g_M2[a * 32 + k] * g_lT2[c * 32 + k];
    g_H[idx] = h + h1 - h2;
}

// lam, bias, D21^T, b_y
__global__ void k_lam_misc(const float* __restrict__ D21, const float* __restrict__ b) {
    int i = threadIdx.x; // 0..255
    float lam = 0.5f * g_H[i * 320 + 64 + i];
    float inv = 1.f / lam;
    g_invlam[i] = inv;
    g_bias[i] = b[64 + i] * inv;
    for (int m = 0; m < 32; m++) g_D21T[i * 32 + m] = D21[m * 256 + i];
    if (i < 32) g_by[i] = b[320 + i];
}

// Combined coefficient matrix, pre-scaled by 1/lam
__global__ void k_build_MT(const float* __restrict__ D12) {
    int i = blockIdx.x; // 0..255
    float inv = g_invlam[i];
    for (int t = threadIdx.x; t < NSTATE; t += blockDim.x) {
        float val;
        if (t < 64) {
            val = -g_H[i * 320 + t] * inv;                 // C_1[i][t] / lam
        } else if (t < 128) {
            val = D12[i * 64 + (t - 64)] * inv;            // D_12[i][t-64] / lam
        } else {
            int j = t - 128;
            // Drows[i][j] = D_11[i-1][j] = -H22[i-1][j] for j <= i-2 (i>=1), else 0
            val = (i >= 1 && j <= i - 2) ? (-g_H[(i - 1) * 320 + 64 + j]) * inv : 0.f;
        }
        g_MT[i * NSTATE + t] = val;
    }
}

// ---------------- main kernel: blocked triangular tanh recurrence ---------

__global__ void __launch_bounds__(TB, 2)
k_main(const float* __restrict__ u, const float* __restrict__ x0,
       const float* __restrict__ C2, float* __restrict__ out) {
    extern __shared__ float sh[];
    float* s_state = sh;                       // [NSTATE][TB]  96 KB
    float* s_m     = sh + NSTATE * TB;         // [8][NSTATE]   12 KB (also y/C2T staging)
    float* s_d21   = s_m + 8 * NSTATE;         // [8][32]        1 KB
    float* s_b     = s_d21 + 256;              // [8]

    const int tid = threadIdx.x;
    const int b0 = blockIdx.x * TB;

    // Load z = [x (64), u (64)] transposed into shared (coalesced global reads)
    for (int idx = tid; idx < TB * 64; idx += TB) {
        int k = idx & 63, bl = idx >> 6;
        s_state[k * TB + bl]        = x0[b0 * 64 + idx];
        s_state[(64 + k) * TB + bl] = u [b0 * 64 + idx];
    }
    __syncthreads();

    // Stage C2 transposed into s_m: s_m[k*32+m] = C2[m][k]
    for (int idx = tid; idx < 64 * 32; idx += TB) {
        int k = idx >> 5, m = idx & 31;
        s_m[idx] = C2[m * 64 + k];
    }
    __syncthreads();

    // y accumulator: x-part  y[m] += x_k * C2[m][k]
    float yacc[32];
#pragma unroll
    for (int m = 0; m < 32; m++) yacc[m] = 0.f;
    for (int k = 0; k < 64; k++) {
        float xv = s_state[k * TB + tid];
#pragma unroll
        for (int m = 0; m < 32; m++) yacc[m] += xv * s_m[k * 32 + m];
    }

    // 32 chunks of 8 units
    for (int c = 0; c < 32; c++) {
        __syncthreads(); // everyone done reading s_m / previous chunk state
        // stage MT rows c*8..c*8+7 (8*384 floats), D21T slice, bias
        {
            const float4* src = (const float4*)(g_MT + c * 8 * NSTATE);
            float4* dst = (float4*)s_m;
            for (int i4 = tid; i4 < 8 * NSTATE / 4; i4 += TB) dst[i4] = src[i4];
            for (int idx = tid; idx < 256; idx += TB) s_d21[idx] = g_D21T[c * 8 * 32 + idx];
            if (tid < 8) s_b[tid] = g_bias[c * 8 + tid];
        }
        __syncthreads();

        float acc[8];
#pragma unroll
        for (int k = 0; k < 8; k++) acc[k] = s_b[k];

        // dense off-diagonal block: z chunks (16) + previous w chunks (c)
        const int pmax = 16 + c;
        for (int p = 0; p < pmax; p++) {
            float sv[8];
#pragma unroll
            for (int j = 0; j < 8; j++) sv[j] = s_state[(p * 8 + j) * TB + tid];
#pragma unroll
            for (int k = 0; k < 8; k++) {
#pragma unroll
                for (int j = 0; j < 8; j++)
                    acc[k] += sv[j] * s_m[k * NSTATE + p * 8 + j];
            }
        }

        // serial 8x8 diagonal block
        float wl[8];
#pragma unroll
        for (int k = 0; k < 8; k++) {
            float s = acc[k];
#pragma unroll
            for (int j = 0; j < 8; j++)
                if (j < k) s += wl[j] * s_m[k * NSTATE + 128 + c * 8 + j];
            wl[k] = tanhf(s);
            s_state[(128 + c * 8 + k) * TB + tid] = wl[k];
        }

        // y accumulation: y[m] += w_j * D21[m][c*8+j]
#pragma unroll
        for (int j = 0; j < 8; j++) {
#pragma unroll
            for (int m = 0; m < 32; m++)
                yacc[m] += wl[j] * s_d21[j * 32 + m];
        }
    }

    // write y through shared for coalesced stores (reuse s_m, padded stride)
    __syncthreads();
#pragma unroll
    for (int m = 0; m < 32; m++) s_m[m * (TB + 1) + tid] = yacc[m] + g_by[m];
    __syncthreads();
    for (int idx = tid; idx < TB * 32; idx += TB) {
        int bl = idx >> 5, m = idx & 31;
        out[(b0 + bl) * 32 + m] = s_m[m * (TB + 1) + bl];
    }
}

// ---------------- launch ----------------

extern "C" void kernel_launch(void* const* d_in, const int* in_sizes, int n_in,
                              void* d_out, int out_size) {
    const float* u    = (const float*)d_in[0];
    const float* x0   = (const float*)d_in[1];
    const float* B2   = (const float*)d_in[2];
    const float* C2   = (const float*)d_in[3];
    const float* D12  = (const float*)d_in[4];
    const float* D21  = (const float*)d_in[5];
    const float* b    = (const float*)d_in[6];
    const float* X    = (const float*)d_in[7];
    // d_in[8] = Y1 (unused by reference)
    const float* St   = (const float*)d_in[9];
    const float* Q    = (const float*)d_in[10];
    const float* Rinv = (const float*)d_in[11];
    float* out = (float*)d_out;

    k_build_lT<<<NZ, 64>>>(B2, C2, D12, D21, St);
    k_build_M<<<NZ, 64>>>(Rinv, Q);
    k_build_H<<<(256 * 320) / 128, 128>>>(X);
    k_lam_misc<<<1, 256>>>(D21, b);
    k_build_MT<<<256, 128>>>(D12);

    const size_t shbytes = (size_t)(NSTATE * TB + 8 * NSTATE + 256 + 8) * sizeof(float);
    cudaFuncSetAttribute(k_main, cudaFuncAttributeMaxDynamicSharedMemorySize, (int)shbytes);
    k_main<<<BATCH / TB, TB, shbytes>>>(u, x0, C2, out);
}

// round 2
// speedup vs baseline: 1.4694x; 1.4694x over previous
#include <cuda_runtime.h>
#include <math.h>

#define NX 64
#define NUN 256
#define NY 32
#define NZ 384        // 2*NX + NUN
#define BATCH 32768
#define NSTATE 384    // 128 (z = x||u) + 256 (w)
#define EPB 128       // batch elements per block
#define PAIRS 64      // f32x2 pairs per block
#define TB 128        // threads per block (2 halves of 64)

typedef unsigned long long ULL;

// ---------------- f32x2 helpers (ptxas only emits FFMA2 from PTX) -------
__device__ __forceinline__ ULL ffma2(ULL a, ULL b, ULL c) {
    ULL d; asm("fma.rn.f32x2 %0, %1, %2, %3;" : "=l"(d) : "l"(a), "l"(b), "l"(c)); return d;
}
__device__ __forceinline__ ULL fadd2(ULL a, ULL b) {
    ULL d; asm("add.rn.f32x2 %0, %1, %2;" : "=l"(d) : "l"(a), "l"(b)); return d;
}
__device__ __forceinline__ ULL pack2(float lo, float hi) {
    ULL d; asm("mov.b64 %0, {%1,%2};" : "=l"(d) : "f"(lo), "f"(hi)); return d;
}
__device__ __forceinline__ void unpack2(ULL v, float& lo, float& hi) {
    asm("mov.b64 {%0,%1}, %2;" : "=f"(lo), "=f"(hi) : "l"(v));
}

// ---------------- device scratch (no cudaMalloc allowed) ----------------
__device__ __align__(16) float g_lT1[NZ * 64];
__device__ __align__(16) float g_lT2[NZ * 32];
__device__ __align__(16) float g_M1[NZ * 64];
__device__ __align__(16) float g_M2[NZ * 32];
__device__ __align__(16) float g_H[256 * 320];     // H[64+r][c], c in [0,320)
__device__ __align__(16) float g_invlam[256];
__device__ __align__(16) float g_MT[256 * NSTATE]; // row i: [C1*il | D12*il | Drows*il]
__device__ __align__(16) float g_bias[256];        // b_w[i] / lam[i]
__device__ __align__(16) float g_D21T[256 * 32];   // [unit][y]

// ---------------- setup kernels (batch-independent weights) --------------

__global__ void k_build_lT(const float* __restrict__ B2, const float* __restrict__ C2,
                           const float* __restrict__ D12, const float* __restrict__ D21,
                           const float* __restrict__ St) {
    int r = blockIdx.x;      // 0..383
    int k = threadIdx.x;     // 0..63
    float v1;
    if (r < 64) {
        float s = 0.f;
        for (int m = 0; m < 32; m++) s += St[k * 32 + m] * C2[m * 64 + r];
        v1 = s;
    } else if (r < 320) {
        int rr = r - 64;
        float s = 0.f;
        for (int m = 0; m < 32; m++) s += St[k * 32 + m] * D21[m * 256 + rr];
        v1 = s - D12[rr * 64 + k];
    } else {
        v1 = B2[(r - 320) * 64 + k];
    }
    g_lT1[r * 64 + k] = v1;
    if (k < 32) {
        float v2;
        if (r < 64)        v2 = C2[k * 64 + r];
        else if (r < 320)  v2 = D21[k * 256 + (r - 64)];
        else               v2 = 0.f;
        g_lT2[r * 32 + k] = v2;
    }
}

__global__ void k_build_M(const float* __restrict__ Rinv, const float* __restrict__ Q) {
    int r = blockIdx.x, k = threadIdx.x;
    float s = 0.f;
    for (int t = 0; t < 64; t++) s += g_lT1[r * 64 + t] * Rinv[t * 64 + k];
    g_M1[r * 64 + k] = s;
    if (k < 32) {
        float s2 = 0.f;
        for (int t = 0; t < 32; t++) s2 += g_lT2[r * 32 + t] * Q[t * 32 + k];
        g_M2[r * 32 + k] = s2;
    }
}

__global__ void k_build_H(const float* __restrict__ X) {
    int idx = blockIdx.x * blockDim.x + threadIdx.x;
    if (idx >= 256 * 320) return;
    int r = idx / 320, c = idx % 320;
    int a = 64 + r;
    float h = 0.f;
    for (int t = 0; t < NZ; t++) h += X[t * NZ + a] * X[t * NZ + c];
    if (c == a) h += 0.001f;
    float h1 = 0.f;
    for (int k = 0; k < 64; k++) h1 += g_M1[a * 64 + k] * g_lT1[c * 64 + k];
    float h2 = 0.f;
    for (int k = 0; k < 32; k++) h2 += g_M2[a * 32 + k] * g_lT2[c * 32 + k];
    g_H[idx] = h + h1 - h2;
}

// lam, bias, D21^T  (parallelized: 256 blocks x 32 threads)
__global__ void k_lam_misc(const float* __restrict__ D21, const float* __restrict__ b) {
    int i = blockIdx.x, m = threadIdx.x;
    g_D21T[i * 32 + m] = D21[m * 256 + i];
    if (m == 0) {
        float lam = 0.5f * g_H[i * 320 + 64 + i];
        float inv = 1.f / lam;
        g_invlam[i] = inv;
        g_bias[i] = b[64 + i] * inv;
    }
}

__global__ void k_build_MT(const float* __restrict__ D12) {
    int i = blockIdx.x; // 0..255
    float inv = g_invlam[i];
    for (int t = threadIdx.x; t < NSTATE; t += blockDim.x) {
        float val;
        if (t < 64) {
            val = -g_H[i * 320 + t] * inv;                 // C_1[i][t] / lam
        } else if (t < 128) {
            val = D12[i * 64 + (t - 64)] * inv;            // D_12 / lam
        } else {
            int j = t - 128;
            val = (i >= 1 && j <= i - 2) ? (-g_H[(i - 1) * 320 + 64 + j]) * inv : 0.f;
        }
        g_MT[i * NSTATE + t] = val;
    }
}

// ---------------- main kernel ---------------------------------------------
// 128 elems/block as 64 f32x2 pairs. 128 threads = 2 "halves" of 64:
//   both halves: partial dot-products over interleaved p-blocks
//   half 0: combine + serial triangular diagonal + tanh + write w
//   half 1: y-GEMM accumulation (one chunk behind) + x-part slices
//
// Shared (ULL units):
//   s_state [384][64]          24576 ULL
//   s_coef  [8][384] (dup)      3072 ULL
//   s_d21   [2][8][32] (dup)     512 ULL
//   s_bias  [8] (dup)              8 ULL
//   s_red   [64][8]              512 ULL
//   s_c2    [4][32] (dup)        128 ULL
//   total 28808 ULL = 230464 B (<= 232448 max dyn smem)

#define SM_STATE 0
#define SM_COEF  (NSTATE * PAIRS)            // 24576
#define SM_D21   (SM_COEF + 8 * NSTATE)      // 27648
#define SM_BIAS  (SM_D21 + 2 * 256)          // 28160
#define SM_RED   (SM_BIAS + 8)               // 28168
#define SM_C2    (SM_RED + PAIRS * 8)        // 28680
#define SM_TOTAL (SM_C2 + 128)               // 28808 ULLs

__global__ void __launch_bounds__(TB, 1)
k_main(const float* __restrict__ u, const float* __restrict__ x0,
       const float* __restrict__ C2, const float* __restrict__ b,
       float* __restrict__ out) {
    extern __shared__ ULL sh[];
    ULL* s_state = sh + SM_STATE;
    ULL* s_coef  = sh + SM_COEF;
    ULL* s_d21   = sh + SM_D21;
    ULL* s_bias  = sh + SM_BIAS;
    ULL* s_red   = sh + SM_RED;
    ULL* s_c2    = sh + SM_C2;

    const int tid  = threadIdx.x;
    const int pair = tid & 63;
    const int half = tid >> 6;
    const int b0   = blockIdx.x * EPB;

    // ---- prefetch chunk 0 coefficients into registers ----
    float4 pf[6];
    float2 pf_d21;
    float  pf_b;
    {
        const float4* src = (const float4*)g_MT;
#pragma unroll
        for (int i = 0; i < 6; i++) pf[i] = src[i * TB + tid];
        pf_d21 = ((const float2*)g_D21T)[tid];
        pf_b   = (tid < 8) ? g_bias[tid] : 0.f;
    }

    // ---- load z = [x(64) | u(64)] into s_state (paired layout) ----
    {
        float* dst = (float*)s_state;
        for (int idx = tid; idx < EPB * 64; idx += TB) {
            int e = idx >> 6, k = idx & 63;
            int off = ((e >> 1)) * 2 + (e & 1);
            dst[(k * PAIRS) * 2 + off]        = x0[b0 * 64 + idx];
            dst[((64 + k) * PAIRS) * 2 + off] = u[b0 * 64 + idx];
        }
    }

    ULL yacc[32];
    if (half) {
#pragma unroll
        for (int m = 0; m < 32; m++) yacc[m] = 0ull;
    }

    for (int c = 0; c < 32; c++) {
        __syncthreads();   // sync1: prior readers of staging buffers done
        // ---- stage chunk c from prefetch regs (duplicated for f32x2) ----
        {
            ulonglong2* dc = (ulonglong2*)s_coef;
#pragma unroll
            for (int i = 0; i < 6; i++) {
                int q = i * TB + tid;
                dc[2 * q]     = make_ulonglong2(pack2(pf[i].x, pf[i].x), pack2(pf[i].y, pf[i].y));
                dc[2 * q + 1] = make_ulonglong2(pack2(pf[i].z, pf[i].z), pack2(pf[i].w, pf[i].w));
            }
            ULL* dd = s_d21 + (c & 1) * 256;
            dd[2 * tid]     = pack2(pf_d21.x, pf_d21.x);
            dd[2 * tid + 1] = pack2(pf_d21.y, pf_d21.y);
            if (tid < 8) s_bias[tid] = pack2(pf_b, pf_b);
            if (c < 16) {   // C2 slice for the y x-part
                int j = tid >> 5, m = tid & 31;
                float v = C2[m * 64 + c * 4 + j];
                s_c2[j * 32 + m] = pack2(v, v);
            }
        }
        // ---- prefetch chunk c+1 ----
        if (c < 31) {
            const float4* src = (const float4*)(g_MT + (c + 1) * 8 * NSTATE);
#pragma unroll
            for (int i = 0; i < 6; i++) pf[i] = src[i * TB + tid];
            pf_d21 = ((const float2*)(g_D21T + (c + 1) * 256))[tid];
            if (tid < 8) pf_b = g_bias[(c + 1) * 8 + tid];
        }
        __syncthreads();   // sync2: staging visible

        // ---- partial accumulation (both halves, interleaved p-blocks) ----
        ULL acc[8];
#pragma unroll
        for (int k = 0; k < 8; k++) acc[k] = 0ull;
        const int P = 16 + c;
        for (int p = half; p < P; p += 2) {
            ULL sv[8];
#pragma unroll
            for (int j = 0; j < 8; j++) sv[j] = s_state[(p * 8 + j) * PAIRS + pair];
#pragma unroll
            for (int k = 0; k < 8; k++) {
                const ulonglong2* cf = (const ulonglong2*)(s_coef + k * NSTATE + p * 8);
                ulonglong2 c0 = cf[0], c1 = cf[1], c2v = cf[2], c3 = cf[3];
                acc[k] = ffma2(sv[0], c0.x, acc[k]);
                acc[k] = ffma2(sv[1], c0.y, acc[k]);
                acc[k] = ffma2(sv[2], c1.x, acc[k]);
                acc[k] = ffma2(sv[3], c1.y, acc[k]);
                acc[k] = ffma2(sv[4], c2v.x, acc[k]);
                acc[k] = ffma2(sv[5], c2v.y, acc[k]);
                acc[k] = ffma2(sv[6], c3.x, acc[k]);
                acc[k] = ffma2(sv[7], c3.y, acc[k]);
            }
        }
        if (half) {
#pragma unroll
            for (int k = 0; k < 8; k++) s_red[pair * 8 + k] = acc[k];
        }
        __syncthreads();   // sync3

        if (!half) {
            // ---- combine + serial triangular diagonal + tanh ----
            ULL wl[8];
#pragma unroll
            for (int k = 0; k < 8; k++) {
                ULL a = fadd2(acc[k], s_red[pair * 8 + k]);
                a = fadd2(a, s_bias[k]);
#pragma unroll
                for (int j = 0; j < 8; j++)
                    if (j < k) a = ffma2(wl[j], s_coef[k * NSTATE + 128 + c * 8 + j], a);
                float lo, hi; unpack2(a, lo, hi);
                wl[k] = pack2(tanhf(lo), tanhf(hi));
                s_state[(128 + c * 8 + k) * PAIRS + pair] = wl[k];
            }
        } else {
            // ---- y accumulation: w chunk c-1, x slice c (runs in parallel with diag) ----
            if (c > 0) {
                ULL wv[8];
#pragma unroll
                for (int j = 0; j < 8; j++)
                    wv[j] = s_state[(128 + (c - 1) * 8 + j) * PAIRS + pair];
                const ULL* dprev = s_d21 + (((c & 1) ^ 1)) * 256;
#pragma unroll
                for (int j = 0; j < 8; j++)
#pragma unroll
                    for (int m = 0; m < 32; m++)
                        yacc[m] = ffma2(wv[j], dprev[j * 32 + m], yacc[m]);
            }
            if (c < 16) {
                ULL xv[4];
#pragma unroll
                for (int j = 0; j < 4; j++) xv[j] = s_state[(c * 4 + j) * PAIRS + pair];
#pragma unroll
                for (int j = 0; j < 4; j++)
#pragma unroll
                    for (int m = 0; m < 32; m++)
                        yacc[m] = ffma2(xv[j], s_c2[j * 32 + m], yacc[m]);
            }
        }
    }

    __syncthreads();
    // ---- final y: w chunk 31 ----
    if (half) {
        ULL wv[8];
#pragma unroll
        for (int j = 0; j < 8; j++) wv[j] = s_state[(128 + 31 * 8 + j) * PAIRS + pair];
        const ULL* dlast = s_d21 + (31 & 1) * 256;
#pragma unroll
        for (int j = 0; j < 8; j++)
#pragma unroll
            for (int m = 0; m < 32; m++)
                yacc[m] = ffma2(wv[j], dlast[j * 32 + m], yacc[m]);
    }
    __syncthreads();   // all s_d21/s_coef readers done before reuse as s_out
    if (half) {
        float* s_out = (float*)s_coef;  // 128*33 floats, spills into staging regions (all dead)
#pragma unroll
        for (int m = 0; m < 32; m++) {
            float by = b[320 + m];
            float lo, hi; unpack2(yacc[m], lo, hi);
            s_out[(2 * pair) * 33 + m]     = lo + by;
            s_out[(2 * pair + 1) * 33 + m] = hi + by;
        }
    }
    __syncthreads();
    {
        const float* s_out = (const float*)s_coef;
        for (int idx = tid; idx < EPB * 32; idx += TB) {
            int e = idx >> 5, m = idx & 31;
            out[(b0 + e) * 32 + m] = s_out[e * 33 + m];
        }
    }
}

// ---------------- launch ----------------

extern "C" void kernel_launch(void* const* d_in, const int* in_sizes, int n_in,
                              void* d_out, int out_size) {
    const float* u    = (const float*)d_in[0];
    const float* x0   = (const float*)d_in[1];
    const float* B2   = (const float*)d_in[2];
    const float* C2   = (const float*)d_in[3];
    const float* D12  = (const float*)d_in[4];
    const float* D21  = (const float*)d_in[5];
    const float* b    = (const float*)d_in[6];
    const float* X    = (const float*)d_in[7];
    // d_in[8] = Y1 (unused by reference)
    const float* St   = (const float*)d_in[9];
    const float* Q    = (const float*)d_in[10];
    const float* Rinv = (const float*)d_in[11];
    float* out = (float*)d_out;

    k_build_lT<<<NZ, 64>>>(B2, C2, D12, D21, St);
    k_build_M<<<NZ, 64>>>(Rinv, Q);
    k_build_H<<<(256 * 320) / 128, 128>>>(X);
    k_lam_misc<<<256, 32>>>(D21, b);
    k_build_MT<<<256, 128>>>(D12);

    const size_t shbytes = (size_t)SM_TOTAL * sizeof(ULL);   // 230464 B
    cudaFuncSetAttribute(k_main, cudaFuncAttributeMaxDynamicSharedMemorySize, (int)shbytes);
    k_main<<<BATCH / EPB, TB, shbytes>>>(u, x0, C2, b, out);
}